// round 13
// baseline (speedup 1.0000x reference)
#include <cuda_runtime.h>
#include <cuda_fp16.h>
#include <cstdint>

// ============================================================================
// SIREN fused inference via fp16 mma.sync m16n8k16 (sm_103-safe PTX).
// R13: one CTA = TWO independent 4-warp groups (split by M half). Each group
// has its own W double-buffer ring and uses NAMED barriers (bar.sync 1+g,128)
// -> groups drift like R11's 2 CTAs (overlapping MUFU/LDSM with the other
// group's HMMA on the same SMSPs) while keeping 64x64 warp tiles (R10/R12's
// low ldmatrix traffic). Numerics: single fp16 A + fp16 W (rel_err 6.6e-4).
// ============================================================================

#define THREADS    256
#define M_TILE     128
#define N_POINTS   1048576
#define GRID_CTAS  (N_POINTS / M_TILE)      // 8192

// --- SMEM layout (bytes) ---
#define A_LDB      528                       // 256 k halves + 16B pad
#define AB_OFF     0                         // single A plane: 128 rows
#define WBUF_OFF   (128 * A_LDB)             // 67584
#define W_LDB      144                       // 64 k halves (128B) + 16B pad
#define W_CHUNK    (256 * W_LDB)             // 36864 (k64 chunk)
// per-group double buffer: group g, buf b at WBUF_OFF + (g*2+b)*W_CHUNK
#define BIAS_OFF   (WBUF_OFF + 4 * W_CHUNK)  // 215040 : b0..b4 (5*256 f32)
#define WFS_OFF    (BIAS_OFF + 5120)         // 220160 : Wf (256 f32)
#define SMEM_TOTAL (WFS_OFF + 1024)          // 221184 <= 232448
// per-group final-reduction buffer reuses the group's own (dead) A rows

// fp16-packed weights: 16 chunks (layer*4 + kc), each 36864B
__device__ __align__(128) unsigned char g_wpacked[16 * W_CHUNK];

// ---------------------------------------------------------------------------
// helpers
// ---------------------------------------------------------------------------
__device__ __forceinline__ uint32_t smem_u32(const void* p) {
    uint32_t a;
    asm("{ .reg .u64 t; cvta.to.shared.u64 t, %1; cvt.u32.u64 %0, t; }"
        : "=r"(a) : "l"(p));
    return a;
}

#define CP_ASYNC16(dst, src) \
    asm volatile("cp.async.cg.shared.global [%0], [%1], 16;" :: "r"(dst), "l"(src) : "memory")
#define CP_COMMIT() asm volatile("cp.async.commit_group;" ::: "memory")
#define CP_WAIT(n)  asm volatile("cp.async.wait_group %0;" :: "n"(n) : "memory")

#define GBAR(id) \
    asm volatile("bar.sync %0, 128;" :: "r"(id) : "memory")

#define LDSM_X4(r0, r1, r2, r3, addr)                                          \
    asm volatile("ldmatrix.sync.aligned.m8n8.x4.shared.b16 {%0,%1,%2,%3}, [%4];" \
        : "=r"(r0), "=r"(r1), "=r"(r2), "=r"(r3) : "r"(addr))

#define MMA_F16(d, a0, a1, a2, a3, b0, b1)                                     \
    asm volatile("mma.sync.aligned.m16n8k16.row.col.f32.f16.f16.f32 "          \
        "{%0,%1,%2,%3}, {%4,%5,%6,%7}, {%8,%9}, {%0,%1,%2,%3};"                \
        : "+f"((d)[0]), "+f"((d)[1]), "+f"((d)[2]), "+f"((d)[3])               \
        : "r"(a0), "r"(a1), "r"(a2), "r"(a3), "r"(b0), "r"(b1))

// single fp16 pack of two fp32
__device__ __forceinline__ uint32_t pack_f16(float z0, float z1) {
    __half2 hp = __halves2half2(__float2half_rn(z0), __float2half_rn(z1));
    return *(uint32_t*)&hp;
}

// ---------------------------------------------------------------------------
// prep: W1..W4 fp32 [256n,256k] -> fp16 k64 chunks, 144B padded rows
// ---------------------------------------------------------------------------
__global__ void prep_weights(const float* __restrict__ W1, const float* __restrict__ W2,
                             const float* __restrict__ W3, const float* __restrict__ W4) {
    int idx = blockIdx.x * blockDim.x + threadIdx.x;   // 65536
    int kg = idx & 63;                                 // 4-k group within 256
    int n  = (idx >> 6) & 255;
    int l  = idx >> 14;
    const float* W = (l == 0) ? W1 : (l == 1) ? W2 : (l == 2) ? W3 : W4;
    int k0 = kg * 4;
    __half2 p01 = __halves2half2(__float2half_rn(W[n * 256 + k0]),
                                 __float2half_rn(W[n * 256 + k0 + 1]));
    __half2 p23 = __halves2half2(__float2half_rn(W[n * 256 + k0 + 2]),
                                 __float2half_rn(W[n * 256 + k0 + 3]));
    int kc = k0 >> 6;                                  // k64 chunk in layer
    int kl = k0 & 63;
    size_t base = (size_t)(l * 4 + kc) * W_CHUNK + (size_t)n * W_LDB + (size_t)kl * 2;
    *(uint2*)(g_wpacked + base) = make_uint2(*(uint32_t*)&p01, *(uint32_t*)&p23);
}

// ---------------------------------------------------------------------------
// main kernel
// ---------------------------------------------------------------------------
// group-local prefetch: 128 threads of the group load one k64 chunk into the
// group's ring buffer (buf = g & 1). 36864B / 128 threads = 18 x 16B each.
__device__ __forceinline__ void prefetch_chunk_g(uint32_t sb, int group, int gtid, int g) {
    const char* src = (const char*)g_wpacked + (size_t)g * W_CHUNK + (size_t)gtid * 16;
    uint32_t dst = sb + WBUF_OFF + (uint32_t)(group * 2 + (g & 1)) * W_CHUNK
                 + (uint32_t)gtid * 16;
#pragma unroll
    for (int i = 0; i < 18; i++)
        CP_ASYNC16(dst + (uint32_t)i * 2048u, src + (size_t)i * 2048);
    CP_COMMIT();
}

__global__ void __launch_bounds__(THREADS, 1)
siren_f16_kernel(const float* __restrict__ xyt, const float* __restrict__ W0,
                 const float* __restrict__ b0, const float* __restrict__ b1,
                 const float* __restrict__ b2, const float* __restrict__ b3,
                 const float* __restrict__ b4, const float* __restrict__ Wf,
                 const float* __restrict__ bfp, float* __restrict__ out) {
    extern __shared__ char smem[];
    const uint32_t sb = smem_u32(smem);
    const int tid = threadIdx.x;
    const int lane = tid & 31;
    const int wid = tid >> 5;
    const int group  = wid & 1;            // M half: rows group*64 .. +64
    const int warp_n = wid >> 1;           // 4 warps over N (64 cols each)
    const int gtid   = (warp_n << 5) + lane;   // 0..127 within group
    const int gbar   = 1 + group;          // named barrier id for this group

    prefetch_chunk_g(sb, group, gtid, 0);  // this group's layer-0 chunks
    prefetch_chunk_g(sb, group, gtid, 1);

    float* bias = (float*)(smem + BIAS_OFF);   // b0..b4
    float* Wfs  = (float*)(smem + WFS_OFF);
    if (tid < 256) {
        bias[tid]        = b0[tid];
        bias[256 + tid]  = b1[tid];
        bias[512 + tid]  = b2[tid];
        bias[768 + tid]  = b3[tid];
        bias[1024 + tid] = b4[tid];
        Wfs[tid] = Wf[tid];
    }
    __syncthreads();   // only full-CTA barrier: params visible to both groups

    // ---- first layer (SIMT, group-local rows): sin(30*(x@W0^T+b0)) -> A ----
    {
        int row   = group * 64 + (gtid >> 1);   // group's own rows
        int cbase = (gtid & 1) * 128;           // 128 n-cols per thread
        int m = blockIdx.x * M_TILE + row;
        float x0 = __ldg(&xyt[3 * m]), x1 = __ldg(&xyt[3 * m + 1]), x2 = __ldg(&xyt[3 * m + 2]);
        char* arow = smem + (uint32_t)row * A_LDB + (uint32_t)cbase * 2;
#pragma unroll 4
        for (int q = 0; q < 64; q++) {
            int n = cbase + 2 * q;
            const float* w = W0 + 3 * n;
            float z0 = fmaf(x0, __ldg(w),     fmaf(x1, __ldg(w + 1), fmaf(x2, __ldg(w + 2), bias[n])));
            float z1 = fmaf(x0, __ldg(w + 3), fmaf(x1, __ldg(w + 4), fmaf(x2, __ldg(w + 5), bias[n + 1])));
            *(uint32_t*)(arow + 4 * q) = pack_f16(__sinf(30.0f * z0), __sinf(30.0f * z1));
        }
    }
    // (first chunk-iteration group barrier gates A visibility within group)

    // ---- 4 hidden layers: 64x64 warp tiles, group-independent schedule ----
#pragma unroll 1
    for (int layer = 0; layer < 4; layer++) {
        float acc[4][8][4];
#pragma unroll
        for (int i = 0; i < 4; i++)
#pragma unroll
            for (int j = 0; j < 8; j++)
#pragma unroll
                for (int e = 0; e < 4; e++) acc[i][j][e] = 0.0f;

#pragma unroll 1
        for (int kc = 0; kc < 4; kc++) {
            int g = layer * 4 + kc;
            if (g == 15) { CP_WAIT(0); } else { CP_WAIT(1); }
            GBAR(gbar);   // buf (g&1) fully loaded by group; A writes visible
            uint32_t wb = sb + WBUF_OFF + (uint32_t)(group * 2 + (g & 1)) * W_CHUNK;

#pragma unroll
            for (int ks = 0; ks < 4; ks++) {
                // B fragments: 4 x4-ldsm covering 64 n-rows x k16
                uint32_t bh[4][4];
#pragma unroll
                for (int jj = 0; jj < 4; jj++) {
                    uint32_t baddr = wb
                        + (uint32_t)((warp_n * 64 + jj * 16 + (lane & 7) + ((lane >> 4) * 8)) * W_LDB)
                        + (uint32_t)(ks * 32 + ((lane >> 3) & 1) * 16);
                    LDSM_X4(bh[jj][0], bh[jj][1], bh[jj][2], bh[jj][3], baddr);
                }
#pragma unroll
                for (int i = 0; i < 4; i++) {
                    uint32_t aaddr = sb
                        + (uint32_t)((group * 64 + i * 16 + (lane & 15)) * A_LDB)
                        + (uint32_t)((kc * 4 + ks) * 32 + (lane >> 4) * 16);
                    uint32_t ah0, ah1, ah2, ah3;
                    LDSM_X4(ah0, ah1, ah2, ah3, aaddr);
#pragma unroll
                    for (int j = 0; j < 8; j++) {
                        uint32_t b0r = bh[j >> 1][(j & 1) * 2];
                        uint32_t b1r = bh[j >> 1][(j & 1) * 2 + 1];
                        MMA_F16(acc[i][j], ah0, ah1, ah2, ah3, b0r, b1r);
                    }
                }
            }
            GBAR(gbar);   // group's reads of buf done -> safe to refill
            if (g + 2 < 16) prefetch_chunk_g(sb, group, gtid, g + 2);
        }
        // last GBAR of the layer also ordered all A reads before the epilogue

        // ---- epilogue (writes only this group's A rows) ----
        if (layer < 3) {
            const float* bs = bias + (layer + 1) * 256;
#pragma unroll
            for (int i = 0; i < 4; i++) {
                int r0 = group * 64 + i * 16 + (lane >> 2);
#pragma unroll
                for (int j = 0; j < 8; j++) {
                    int n0 = warp_n * 64 + j * 8 + (lane & 3) * 2;
                    uint32_t off = (uint32_t)(r0 * A_LDB + n0 * 2);
                    float bb0 = bs[n0], bb1 = bs[n0 + 1];
                    *(uint32_t*)(smem + off) =
                        pack_f16(__sinf(acc[i][j][0] + bb0), __sinf(acc[i][j][1] + bb1));
                    *(uint32_t*)(smem + off + 8u * A_LDB) =
                        pack_f16(__sinf(acc[i][j][2] + bb0), __sinf(acc[i][j][3] + bb1));
                }
            }
            // next layer's first GBAR gates these writes within the group
        } else {
            // final: out[m] = sum_n sin(z[m,n]) * Wf[n] + bf
            const float* bs = bias + 1024;
            // per-group reduction buffer inside the group's own dead A rows
            float* red = (float*)(smem + AB_OFF + (uint32_t)group * 64u * A_LDB);
#pragma unroll
            for (int i = 0; i < 4; i++) {
                float p0 = 0.0f, p1 = 0.0f;
#pragma unroll
                for (int j = 0; j < 8; j++) {
                    int n0 = warp_n * 64 + j * 8 + (lane & 3) * 2;
                    p0 = fmaf(__sinf(acc[i][j][0] + bs[n0]),     Wfs[n0],     p0);
                    p0 = fmaf(__sinf(acc[i][j][1] + bs[n0 + 1]), Wfs[n0 + 1], p0);
                    p1 = fmaf(__sinf(acc[i][j][2] + bs[n0]),     Wfs[n0],     p1);
                    p1 = fmaf(__sinf(acc[i][j][3] + bs[n0 + 1]), Wfs[n0 + 1], p1);
                }
                p0 += __shfl_xor_sync(0xffffffffu, p0, 1);
                p0 += __shfl_xor_sync(0xffffffffu, p0, 2);
                p1 += __shfl_xor_sync(0xffffffffu, p1, 1);
                p1 += __shfl_xor_sync(0xffffffffu, p1, 2);
                if ((lane & 3) == 0) {
                    int rl = i * 16 + (lane >> 2);      // 0..63 within group
                    red[rl * 4 + warp_n]       = p0;
                    red[(rl + 8) * 4 + warp_n] = p1;
                }
            }
            GBAR(gbar);
            if (warp_n == 0) {   // warp `group` writes the group's 64 outputs
#pragma unroll
                for (int h = 0; h < 2; h++) {
                    int rl = h * 32 + lane;
                    float s = red[rl * 4] + red[rl * 4 + 1] +
                              red[rl * 4 + 2] + red[rl * 4 + 3] + bfp[0];
                    out[(size_t)blockIdx.x * M_TILE + group * 64 + rl] = s;
                }
            }
        }
    }
}

// ---------------------------------------------------------------------------
// kernel_launch
// ---------------------------------------------------------------------------
extern "C" void kernel_launch(void* const* d_in, const int* in_sizes, int n_in,
                              void* d_out, int out_size) {
    const float* xyt = (const float*)d_in[0];
    const float* W0  = (const float*)d_in[1];
    const float* b0  = (const float*)d_in[2];
    const float* W1  = (const float*)d_in[3];
    const float* b1  = (const float*)d_in[4];
    const float* W2  = (const float*)d_in[5];
    const float* b2  = (const float*)d_in[6];
    const float* W3  = (const float*)d_in[7];
    const float* b3  = (const float*)d_in[8];
    const float* W4  = (const float*)d_in[9];
    const float* b4  = (const float*)d_in[10];
    const float* Wf  = (const float*)d_in[11];
    const float* bf  = (const float*)d_in[12];
    float* out = (float*)d_out;
    (void)in_sizes; (void)n_in; (void)out_size;

    cudaFuncSetAttribute(siren_f16_kernel,
                         cudaFuncAttributeMaxDynamicSharedMemorySize, SMEM_TOTAL);

    prep_weights<<<256, 256>>>(W1, W2, W3, W4);
    siren_f16_kernel<<<GRID_CTAS, THREADS, SMEM_TOTAL>>>(
        xyt, W0, b0, b1, b2, b3, b4, Wf, bf, out);
}

// round 14
// speedup vs baseline: 1.1096x; 1.1096x over previous
#include <cuda_runtime.h>
#include <cuda_fp16.h>
#include <cstdint>

// ============================================================================
// SIREN fused inference via fp16 mma.sync m16n8k16 (sm_103-safe PTX).
// R14 = R11 (M64, 2 CTAs/SM, 32x64 warp tiles) with the 32 CTA-wide
// __syncthreads replaced by dependency-scoped barriers:
//  - W chunks sliced per warp-PAIR (pair = warp_n); warp_m=0 of each pair
//    owns cp.async for its 9216B slice; recycle via 64-thread bar.sync.
//  - A-plane hazards via 128-thread m-group barriers, 2 per layer.
//  - acc initialized with bias (free bias add).
// 8 pair-pipelines per SM drift freely -> LDSM/MUFU/cp overlap HMMA.
// Numerics: single fp16 activations + fp16 weights (rel_err 6.6e-4).
// ============================================================================

#define THREADS    256
#define M_TILE     64
#define N_POINTS   1048576
#define GRID_CTAS  (N_POINTS / M_TILE)      // 16384

// --- SMEM layout (bytes) ---
#define A_LDB      528                       // 256 k halves + 16B pad
#define AB_OFF     0                         // single A plane: 64 rows
#define WBUF_OFF   (64 * A_LDB)              // 33792
#define W_LDB      144                       // 64 k halves (128B) + 16B pad
#define W_CHUNK    (256 * W_LDB)             // 36864 (k64 chunk, prep layout)
#define W_SLICE    (64 * W_LDB)              // 9216 (pair's 64 B-rows)
// pair p, slot s at WBUF_OFF + (p*2+s)*W_SLICE ; 8 slices = 73728
#define BIAS_OFF   (WBUF_OFF + 8 * W_SLICE)  // 107520 : b0..b4 (5*256 f32)
#define WFS_OFF    (BIAS_OFF + 5120)         // 112640 : Wf (256 f32)
#define SMEM_TOTAL (WFS_OFF + 1024)          // 113664 -> 2 CTAs/SM
// final-reduction buffer reuses the (dead) A area

// fp16-packed weights: 16 chunks (layer*4 + kc), each 36864B
__device__ __align__(128) unsigned char g_wpacked[16 * W_CHUNK];

// ---------------------------------------------------------------------------
// helpers
// ---------------------------------------------------------------------------
__device__ __forceinline__ uint32_t smem_u32(const void* p) {
    uint32_t a;
    asm("{ .reg .u64 t; cvta.to.shared.u64 t, %1; cvt.u32.u64 %0, t; }"
        : "=r"(a) : "l"(p));
    return a;
}

#define CP_ASYNC16(dst, src) \
    asm volatile("cp.async.cg.shared.global [%0], [%1], 16;" :: "r"(dst), "l"(src) : "memory")
#define CP_COMMIT() asm volatile("cp.async.commit_group;" ::: "memory")
#define CP_WAIT(n)  asm volatile("cp.async.wait_group %0;" :: "n"(n) : "memory")

#define NBAR(id, cnt) \
    asm volatile("bar.sync %0, %1;" :: "r"(id), "r"(cnt) : "memory")

#define LDSM_X4(r0, r1, r2, r3, addr)                                          \
    asm volatile("ldmatrix.sync.aligned.m8n8.x4.shared.b16 {%0,%1,%2,%3}, [%4];" \
        : "=r"(r0), "=r"(r1), "=r"(r2), "=r"(r3) : "r"(addr))

#define MMA_F16(d, a0, a1, a2, a3, b0, b1)                                     \
    asm volatile("mma.sync.aligned.m16n8k16.row.col.f32.f16.f16.f32 "          \
        "{%0,%1,%2,%3}, {%4,%5,%6,%7}, {%8,%9}, {%0,%1,%2,%3};"                \
        : "+f"((d)[0]), "+f"((d)[1]), "+f"((d)[2]), "+f"((d)[3])               \
        : "r"(a0), "r"(a1), "r"(a2), "r"(a3), "r"(b0), "r"(b1))

// single fp16 pack of two fp32
__device__ __forceinline__ uint32_t pack_f16(float z0, float z1) {
    __half2 hp = __halves2half2(__float2half_rn(z0), __float2half_rn(z1));
    return *(uint32_t*)&hp;
}

// ---------------------------------------------------------------------------
// prep: W1..W4 fp32 [256n,256k] -> fp16 k64 chunks, 144B padded rows
// ---------------------------------------------------------------------------
__global__ void prep_weights(const float* __restrict__ W1, const float* __restrict__ W2,
                             const float* __restrict__ W3, const float* __restrict__ W4) {
    int idx = blockIdx.x * blockDim.x + threadIdx.x;   // 65536
    int kg = idx & 63;                                 // 4-k group within 256
    int n  = (idx >> 6) & 255;
    int l  = idx >> 14;
    const float* W = (l == 0) ? W1 : (l == 1) ? W2 : (l == 2) ? W3 : W4;
    int k0 = kg * 4;
    __half2 p01 = __halves2half2(__float2half_rn(W[n * 256 + k0]),
                                 __float2half_rn(W[n * 256 + k0 + 1]));
    __half2 p23 = __halves2half2(__float2half_rn(W[n * 256 + k0 + 2]),
                                 __float2half_rn(W[n * 256 + k0 + 3]));
    int kc = k0 >> 6;                                  // k64 chunk in layer
    int kl = k0 & 63;
    size_t base = (size_t)(l * 4 + kc) * W_CHUNK + (size_t)n * W_LDB + (size_t)kl * 2;
    *(uint2*)(g_wpacked + base) = make_uint2(*(uint32_t*)&p01, *(uint32_t*)&p23);
}

// ---------------------------------------------------------------------------
// main kernel
// ---------------------------------------------------------------------------
// issuer warp (warp_m==0) loads its pair's 64-row slice of chunk g.
// 9216B / 32 lanes = 288B = 18 x 16B per lane.
__device__ __forceinline__ void prefetch_slice(uint32_t sb, int pair, int lane, int g) {
    const char* src = (const char*)g_wpacked + (size_t)g * W_CHUNK
                    + (size_t)pair * W_SLICE + (size_t)lane * 16;
    uint32_t dst = sb + WBUF_OFF + (uint32_t)(pair * 2 + (g & 1)) * W_SLICE
                 + (uint32_t)lane * 16u;
#pragma unroll
    for (int i = 0; i < 18; i++)
        CP_ASYNC16(dst + (uint32_t)i * 512u, src + (size_t)i * 512);
    CP_COMMIT();
}

__global__ void __launch_bounds__(THREADS, 2)
siren_f16_kernel(const float* __restrict__ xyt, const float* __restrict__ W0,
                 const float* __restrict__ b0, const float* __restrict__ b1,
                 const float* __restrict__ b2, const float* __restrict__ b3,
                 const float* __restrict__ b4, const float* __restrict__ Wf,
                 const float* __restrict__ bfp, float* __restrict__ out) {
    extern __shared__ char smem[];
    const uint32_t sb = smem_u32(smem);
    const int tid = threadIdx.x;
    const int lane = tid & 31;
    const int wid = tid >> 5;
    const int warp_m = wid & 1;    // 2 warp-rows over M (32 rows each)
    const int warp_n = wid >> 1;   // 4 warp-slices over N (64 cols each)
    const int pair   = warp_n;     // W-slice ownership group (2 warps)
    const bool issuer = (warp_m == 0);
    const int pbar = 1 + pair;     // named barrier for the pair (64 thr)
    const int mbar = 5 + warp_m;   // named barrier for the m-group (128 thr)

    if (issuer) {                  // start this pair's W stream immediately
        prefetch_slice(sb, pair, lane, 0);
        prefetch_slice(sb, pair, lane, 1);
    }

    float* bias = (float*)(smem + BIAS_OFF);   // b0..b4
    float* Wfs  = (float*)(smem + WFS_OFF);
    if (tid < 256) {
        bias[tid]        = b0[tid];
        bias[256 + tid]  = b1[tid];
        bias[512 + tid]  = b2[tid];
        bias[768 + tid]  = b3[tid];
        bias[1024 + tid] = b4[tid];
        Wfs[tid] = Wf[tid];
    }
    __syncthreads();

    // ---- first layer (SIMT): sin(30*(x@W0^T+b0)) -> A plane ----
    {
        int row   = tid >> 2;                  // 0..63
        int cbase = (tid & 3) * 64;            // 64 n-cols per thread
        int m = blockIdx.x * M_TILE + row;
        float x0 = __ldg(&xyt[3 * m]), x1 = __ldg(&xyt[3 * m + 1]), x2 = __ldg(&xyt[3 * m + 2]);
        char* arow = smem + (uint32_t)row * A_LDB + (uint32_t)cbase * 2;
#pragma unroll 4
        for (int q = 0; q < 32; q++) {
            int n = cbase + 2 * q;
            const float* w = W0 + 3 * n;
            float z0 = fmaf(x0, __ldg(w),     fmaf(x1, __ldg(w + 1), fmaf(x2, __ldg(w + 2), bias[n])));
            float z1 = fmaf(x0, __ldg(w + 3), fmaf(x1, __ldg(w + 4), fmaf(x2, __ldg(w + 5), bias[n + 1])));
            *(uint32_t*)(arow + 4 * q) = pack_f16(__sinf(30.0f * z0), __sinf(30.0f * z1));
        }
    }
    __syncthreads();   // A visible to all warps (writers span all warps)

    // ---- 4 hidden layers: pair-autonomous W pipeline ----
#pragma unroll 1
    for (int layer = 0; layer < 4; layer++) {
        // init acc with the NEXT bias (free bias add; layer 3 -> b4)
        const float* bsi = bias + (layer + 1) * 256;
        float acc[2][8][4];
#pragma unroll
        for (int j = 0; j < 8; j++) {
            int n0 = warp_n * 64 + j * 8 + (lane & 3) * 2;
            float bv0 = bsi[n0], bv1 = bsi[n0 + 1];
            acc[0][j][0] = bv0; acc[0][j][1] = bv1; acc[0][j][2] = bv0; acc[0][j][3] = bv1;
            acc[1][j][0] = bv0; acc[1][j][1] = bv1; acc[1][j][2] = bv0; acc[1][j][3] = bv1;
        }

#pragma unroll 1
        for (int kc = 0; kc < 4; kc++) {
            int g = layer * 4 + kc;
            if (issuer) {
                if (g == 15) { CP_WAIT(0); } else { CP_WAIT(1); }
            }
            NBAR(pbar, 64);    // slice g visible to both pair warps
            uint32_t wb = sb + WBUF_OFF + (uint32_t)(pair * 2 + (g & 1)) * W_SLICE;

#pragma unroll
            for (int ks = 0; ks < 4; ks++) {
                uint32_t bh[4][4];
#pragma unroll
                for (int jj = 0; jj < 4; jj++) {
                    uint32_t baddr = wb
                        + (uint32_t)((jj * 16 + (lane & 7) + ((lane >> 4) * 8)) * W_LDB)
                        + (uint32_t)(ks * 32 + ((lane >> 3) & 1) * 16);
                    LDSM_X4(bh[jj][0], bh[jj][1], bh[jj][2], bh[jj][3], baddr);
                }
#pragma unroll
                for (int i = 0; i < 2; i++) {
                    uint32_t aaddr = sb
                        + (uint32_t)((warp_m * 32 + i * 16 + (lane & 15)) * A_LDB)
                        + (uint32_t)((kc * 4 + ks) * 32 + (lane >> 4) * 16);
                    uint32_t ah0, ah1, ah2, ah3;
                    LDSM_X4(ah0, ah1, ah2, ah3, aaddr);
#pragma unroll
                    for (int j = 0; j < 8; j++) {
                        uint32_t b0r = bh[j >> 1][(j & 1) * 2];
                        uint32_t b1r = bh[j >> 1][(j & 1) * 2 + 1];
                        MMA_F16(acc[i][j], ah0, ah1, ah2, ah3, b0r, b1r);
                    }
                }
            }
            NBAR(pbar, 64);    // both pair warps done reading slot (g&1)
            if (issuer && g + 2 < 16) prefetch_slice(sb, pair, lane, g + 2);
        }

        // m-group barrier: all 4 same-warp_m warps finished reading A rows
        NBAR(mbar, 128);

        // ---- epilogue (bias already in acc) ----
        if (layer < 3) {
#pragma unroll
            for (int i = 0; i < 2; i++) {
                int r0 = warp_m * 32 + i * 16 + (lane >> 2);
#pragma unroll
                for (int j = 0; j < 8; j++) {
                    int n0 = warp_n * 64 + j * 8 + (lane & 3) * 2;
                    uint32_t off = (uint32_t)(r0 * A_LDB + n0 * 2);
                    *(uint32_t*)(smem + off) =
                        pack_f16(__sinf(acc[i][j][0]), __sinf(acc[i][j][1]));
                    *(uint32_t*)(smem + off + 8u * A_LDB) =
                        pack_f16(__sinf(acc[i][j][2]), __sinf(acc[i][j][3]));
                }
            }
            NBAR(mbar, 128);   // A writes visible to the m-group's readers
        } else {
            // final: out[m] = sum_n sin(z[m,n]) * Wf[n] + bf
            float* red = (float*)(smem + AB_OFF);   // reuse dead A area
#pragma unroll
            for (int i = 0; i < 2; i++) {
                float p0 = 0.0f, p1 = 0.0f;
#pragma unroll
                for (int j = 0; j < 8; j++) {
                    int n0 = warp_n * 64 + j * 8 + (lane & 3) * 2;
                    p0 = fmaf(__sinf(acc[i][j][0]), Wfs[n0],     p0);
                    p0 = fmaf(__sinf(acc[i][j][1]), Wfs[n0 + 1], p0);
                    p1 = fmaf(__sinf(acc[i][j][2]), Wfs[n0],     p1);
                    p1 = fmaf(__sinf(acc[i][j][3]), Wfs[n0 + 1], p1);
                }
                p0 += __shfl_xor_sync(0xffffffffu, p0, 1);
                p0 += __shfl_xor_sync(0xffffffffu, p0, 2);
                p1 += __shfl_xor_sync(0xffffffffu, p1, 1);
                p1 += __shfl_xor_sync(0xffffffffu, p1, 2);
                if ((lane & 3) == 0) {
                    int r0 = warp_m * 32 + i * 16 + (lane >> 2);
                    red[r0 * 4 + warp_n]       = p0;
                    red[(r0 + 8) * 4 + warp_n] = p1;
                }
            }
            __syncthreads();   // all warps' red writes visible
            if (tid < 64) {
                float s = red[tid * 4] + red[tid * 4 + 1] +
                          red[tid * 4 + 2] + red[tid * 4 + 3] + bfp[0];
                out[(size_t)blockIdx.x * M_TILE + tid] = s;
            }
        }
    }
}

// ---------------------------------------------------------------------------
// kernel_launch
// ---------------------------------------------------------------------------
extern "C" void kernel_launch(void* const* d_in, const int* in_sizes, int n_in,
                              void* d_out, int out_size) {
    const float* xyt = (const float*)d_in[0];
    const float* W0  = (const float*)d_in[1];
    const float* b0  = (const float*)d_in[2];
    const float* W1  = (const float*)d_in[3];
    const float* b1  = (const float*)d_in[4];
    const float* W2  = (const float*)d_in[5];
    const float* b2  = (const float*)d_in[6];
    const float* W3  = (const float*)d_in[7];
    const float* b3  = (const float*)d_in[8];
    const float* W4  = (const float*)d_in[9];
    const float* b4  = (const float*)d_in[10];
    const float* Wf  = (const float*)d_in[11];
    const float* bf  = (const float*)d_in[12];
    float* out = (float*)d_out;
    (void)in_sizes; (void)n_in; (void)out_size;

    cudaFuncSetAttribute(siren_f16_kernel,
                         cudaFuncAttributeMaxDynamicSharedMemorySize, SMEM_TOTAL);

    prep_weights<<<256, 256>>>(W1, W2, W3, W4);
    siren_f16_kernel<<<GRID_CTAS, THREADS, SMEM_TOTAL>>>(
        xyt, W0, b0, b1, b2, b3, b4, Wf, bf, out);
}